// round 10
// baseline (speedup 1.0000x reference)
#include <cuda_runtime.h>
#include <cuda_fp16.h>
#include <cstdint>
#include <cstddef>

#define N_NODES 16384
#define IN_F    128
#define OUT_F   64
#define NV      72      // V cols: 64 feats + ones col (denominator) + 7 pad
#define BI      64      // rows per CTA
#define BJ      128     // j-tile width
#define PSS     136     // P row stride (halves), conflict-free for ldmatrix
#define JSPLIT  8
#define JTILES  (N_NODES / JSPLIT / BJ)   // 16
#define IBLOCKS (N_NODES / BI)            // 256

#define PS_BYTES (BI * PSS * 2)           // 17408
#define VS_BYTES (BJ * NV * 2)            // 18432
#define SMEM_TOTAL (2 * PS_BYTES + 2 * VS_BYTES + BI * 16)  // 72704

// Scratch (device globals: allocation-free rule)
__device__ __align__(16) float  g_Wh[N_NODES * OUT_F];
__device__ __align__(16) __half g_V [N_NODES * NV];
__device__ __align__(16) float4 g_rowc[N_NODES];   // {-fi, e^fi, e^{.02fi}, 0}
__device__ __align__(16) float4 g_colc[N_NODES];   // { fj, e^fj, e^{.02fj}, 0}
__device__ __align__(16) float  g_part[(size_t)JSPLIT * N_NODES * NV];  // 37.7MB

// ---------------------------------------------------------------------------
// Kernel A: Wh = x @ W (fp32) + fp16 V with ones column
// ---------------------------------------------------------------------------
__global__ __launch_bounds__(256) void wh_kernel(const float* __restrict__ x,
                                                 const float* __restrict__ w) {
    __shared__ float ws[IN_F * OUT_F];
    int tid = threadIdx.x;
    for (int t = tid; t < IN_F * OUT_F; t += 256) ws[t] = w[t];
    __syncthreads();

    int rl  = tid >> 3;
    int c0  = (tid & 7) * 8;
    int row = blockIdx.x * 32 + rl;

    float acc[8];
#pragma unroll
    for (int j = 0; j < 8; j++) acc[j] = 0.f;

    const float4* xr = (const float4*)(x + (size_t)row * IN_F);
#pragma unroll 8
    for (int q = 0; q < 32; q++) {
        float4 xv = __ldg(&xr[q]);
        int k = q * 4;
#pragma unroll
        for (int j = 0; j < 8; j++) acc[j] = fmaf(xv.x, ws[(k + 0) * OUT_F + c0 + j], acc[j]);
#pragma unroll
        for (int j = 0; j < 8; j++) acc[j] = fmaf(xv.y, ws[(k + 1) * OUT_F + c0 + j], acc[j]);
#pragma unroll
        for (int j = 0; j < 8; j++) acc[j] = fmaf(xv.z, ws[(k + 2) * OUT_F + c0 + j], acc[j]);
#pragma unroll
        for (int j = 0; j < 8; j++) acc[j] = fmaf(xv.w, ws[(k + 3) * OUT_F + c0 + j], acc[j]);
    }
#pragma unroll
    for (int j = 0; j < 8; j++) {
        g_Wh[(size_t)row * OUT_F + c0 + j] = acc[j];
        g_V[(size_t)row * NV + c0 + j]     = __float2half(acc[j]);
    }
    if ((tid & 7) == 0) {
        g_V[(size_t)row * NV + 64] = __float2half(1.0f);
#pragma unroll
        for (int t = 65; t < NV; t++) g_V[(size_t)row * NV + t] = __float2half(0.0f);
    }
}

// ---------------------------------------------------------------------------
// Kernel B: attention scalars + exp tables
// ---------------------------------------------------------------------------
__global__ __launch_bounds__(256) void f_kernel(const float* __restrict__ aw) {
    int r = blockIdx.x * blockDim.x + threadIdx.x;
    const float4* whr = (const float4*)(g_Wh + (size_t)r * OUT_F);
    float fi = 0.f, fj = 0.f;
#pragma unroll
    for (int q = 0; q < 16; q++) {
        float4 v = whr[q];
        fi += v.x * __ldg(&aw[q * 4 + 0]) + v.y * __ldg(&aw[q * 4 + 1])
            + v.z * __ldg(&aw[q * 4 + 2]) + v.w * __ldg(&aw[q * 4 + 3]);
        fj += v.x * __ldg(&aw[64 + q * 4 + 0]) + v.y * __ldg(&aw[64 + q * 4 + 1])
            + v.z * __ldg(&aw[64 + q * 4 + 2]) + v.w * __ldg(&aw[64 + q * 4 + 3]);
    }
    g_rowc[r] = make_float4(-fi, expf(fi), expf(0.02f * fi), 0.f);
    g_colc[r] = make_float4(fj,  expf(fj), expf(0.02f * fj), 0.f);
}

// ---------------------------------------------------------------------------
// Full-tile MMA (8 k-steps), per warp M=16: C[9][4] += P[16x128] @ V[128x72].
// B loaded with x4.trans (two n-tiles per LDSM).
// ---------------------------------------------------------------------------
__device__ __forceinline__ void mma_full(uint32_t abase, uint32_t vbase, int lane,
                                         float (&c)[9][4]) {
#pragma unroll
    for (int kk = 0; kk < 8; kk++) {
        uint32_t A[4];
        asm volatile("ldmatrix.sync.aligned.m8n8.x4.shared.b16 {%0,%1,%2,%3}, [%4];"
                     : "=r"(A[0]), "=r"(A[1]), "=r"(A[2]), "=r"(A[3])
                     : "r"(abase + kk * 32));
        uint32_t B[9][2];
        uint32_t brow = vbase + 2u * ((kk * 16 + (lane & 15)) * NV) + ((lane >> 4) << 4);
#pragma unroll
        for (int gp = 0; gp < 4; gp++) {
            asm volatile("ldmatrix.sync.aligned.m8n8.x4.trans.shared.b16 {%0,%1,%2,%3}, [%4];"
                         : "=r"(B[2 * gp][0]), "=r"(B[2 * gp][1]),
                           "=r"(B[2 * gp + 1][0]), "=r"(B[2 * gp + 1][1])
                         : "r"(brow + gp * 32));
        }
        asm volatile("ldmatrix.sync.aligned.m8n8.x2.trans.shared.b16 {%0,%1}, [%2];"
                     : "=r"(B[8][0]), "=r"(B[8][1])
                     : "r"(vbase + 2u * ((kk * 16 + (lane & 15)) * NV) + 128));
#pragma unroll
        for (int ng = 0; ng < 9; ng++)
            asm volatile("mma.sync.aligned.m16n8k16.row.col.f32.f16.f16.f32 "
                         "{%0,%1,%2,%3}, {%4,%5,%6,%7}, {%8,%9}, {%0,%1,%2,%3};"
                         : "+f"(c[ng][0]), "+f"(c[ng][1]), "+f"(c[ng][2]), "+f"(c[ng][3])
                         : "r"(A[0]), "r"(A[1]), "r"(A[2]), "r"(A[3]),
                           "r"(B[ng][0]), "r"(B[ng][1]));
    }
}

// ---------------------------------------------------------------------------
// Main fused kernel, warp-specialized:
//   warps 0-3: MMA consumers (M=16 each over BI=64)
//   warps 4-7: producers (V tile + adj stream + P tile)
// 3 CTAs/SM -> 24 warps/SM. Double-buffered, one barrier per tile.
// ---------------------------------------------------------------------------
__global__ __launch_bounds__(256, 3) void gat_main(const int* __restrict__ adj) {
    extern __shared__ __align__(16) char sm[];
    __half* Ps = (__half*)sm;
    __half* Vs = (__half*)(sm + 2 * PS_BYTES);
    float4* rowc = (float4*)(sm + 2 * PS_BYTES + 2 * VS_BYTES);

    int tid  = threadIdx.x;
    int lane = tid & 31;
    int warp = tid >> 5;
    int i0    = blockIdx.x * BI;
    int jbase = blockIdx.y * (N_NODES / JSPLIT);

    if (tid < BI) rowc[tid] = g_rowc[i0 + tid];
    __syncthreads();

    uint32_t ps_u = (uint32_t)__cvta_generic_to_shared(Ps);
    uint32_t vs_u = (uint32_t)__cvta_generic_to_shared(Vs);

    if (warp < 4) {
        // ================= CONSUMER =================
        float c[9][4];
#pragma unroll
        for (int ng = 0; ng < 9; ng++)
#pragma unroll
            for (int q = 0; q < 4; q++) c[ng][q] = 0.f;

        int m0 = warp * 16;
        uint32_t a_off = 2u * ((m0 + (lane & 15)) * PSS + (lane >> 4) * 8);

#pragma unroll 1
        for (int t = 0; t < JTILES; t++) {
            int buf = t & 1;
            if (t > 0)
                mma_full(ps_u + (buf ^ 1) * PS_BYTES + a_off,
                         vs_u + (buf ^ 1) * VS_BYTES, lane, c);
            __syncthreads();
        }
        // drain last tile
        {
            int buf = (JTILES - 1) & 1;
            mma_full(ps_u + buf * PS_BYTES + a_off, vs_u + buf * VS_BYTES, lane, c);
        }

        // store partials (numerator cols 0..63, denom col 64)
        float* pp = g_part + ((size_t)blockIdx.y * N_NODES + i0) * NV;
        int r0 = m0 + (lane >> 2);
        int cb = (lane & 3) * 2;
#pragma unroll
        for (int ng = 0; ng < 9; ng++) {
            *(float2*)&pp[(size_t)r0 * NV + ng * 8 + cb]       = make_float2(c[ng][0], c[ng][1]);
            *(float2*)&pp[(size_t)(r0 + 8) * NV + ng * 8 + cb] = make_float2(c[ng][2], c[ng][3]);
        }
    } else {
        // ================= PRODUCER =================
        int ptid  = tid - 128;          // 0..127
        int rhalf = ptid >> 6;          // rows rhalf*32 .. +32
        int c0    = (ptid & 63) * 2;    // column pair

#pragma unroll 1
        for (int t = 0; t < JTILES; t++) {
            int j0  = jbase + t * BJ;
            int buf = t & 1;

            // V tile into buf: 1152 uint4 over 128 threads
            {
                const uint4* vsrc = (const uint4*)(g_V + (size_t)j0 * NV);
                uint4* vdst = (uint4*)(Vs + buf * (BJ * NV));
#pragma unroll
                for (int q = 0; q < 9; q++)
                    vdst[ptid + q * 128] = vsrc[ptid + q * 128];
            }

            float4 C0 = __ldg(&g_colc[j0 + c0]);
            float4 C1 = __ldg(&g_colc[j0 + c0 + 1]);
            const int* adjp = adj + (size_t)(i0 + rhalf * 32) * N_NODES + j0 + c0;
            __half* Psb = Ps + buf * (BI * PSS);

#pragma unroll
            for (int b = 0; b < 2; b++) {
                int2 av[16];
#pragma unroll
                for (int u = 0; u < 16; u++)
                    av[u] = __ldg((const int2*)(adjp + (size_t)(b * 16 + u) * N_NODES));
#pragma unroll
                for (int u = 0; u < 16; u++) {
                    int row = rhalf * 32 + b * 16 + u;
                    float4 R = rowc[row];                 // broadcast LDS.128
                    bool s0 = C0.x > R.x;                 // fj > -fi
                    bool s1 = C1.x > R.x;
                    float v0 = (s0 ? R.y : R.z) * (s0 ? C0.y : C0.z);
                    float v1 = (s1 ? R.y : R.z) * (s1 ? C1.y : C1.z);
                    v0 = av[u].x > 0 ? v0 : 0.f;
                    v1 = av[u].y > 0 ? v1 : 0.f;
                    *(__half2*)&Psb[row * PSS + c0] = __floats2half2_rn(v0, v1);
                }
            }
            __syncthreads();   // single barrier per tile
        }
    }
}

// ---------------------------------------------------------------------------
// Reduce: sum 8 split-partials, divide by denom (col 64), ELU, store.
// ---------------------------------------------------------------------------
__global__ __launch_bounds__(128) void reduce_kernel(float* __restrict__ out) {
    int tid = threadIdx.x;
    int row = blockIdx.x * 4 + (tid >> 5);
    int cp  = tid & 31;

    size_t base = (size_t)row * NV;
    float denom = 0.f, n0 = 0.f, n1 = 0.f;
#pragma unroll
    for (int s = 0; s < JSPLIT; s++) {
        const float* p = g_part + (size_t)s * N_NODES * NV + base;
        denom += __ldg(&p[64]);
        float2 v = *(const float2*)(p + 2 * cp);
        n0 += v.x;
        n1 += v.y;
    }
    float inv = 1.0f / denom;
    float h0 = n0 * inv, h1 = n1 * inv;
    h0 = h0 > 0.f ? h0 : expm1f(h0);
    h1 = h1 > 0.f ? h1 : expm1f(h1);
    *(float2*)&out[(size_t)row * OUT_F + 2 * cp] = make_float2(h0, h1);
}

// ---------------------------------------------------------------------------
extern "C" void kernel_launch(void* const* d_in, const int* in_sizes, int n_in,
                              void* d_out, int out_size) {
    const float* x   = (const float*)d_in[0];   // [16384, 128] f32
    const int*   adj = (const int*)d_in[1];     // [16384, 16384] i32
    const float* w   = (const float*)d_in[2];   // [128, 64] f32
    const float* aw  = (const float*)d_in[3];   // [128, 1] f32
    float* out = (float*)d_out;                 // [16384, 64] f32

    cudaFuncSetAttribute(gat_main, cudaFuncAttributeMaxDynamicSharedMemorySize,
                         SMEM_TOTAL);

    wh_kernel<<<N_NODES / 32, 256>>>(x, w);
    f_kernel<<<N_NODES / 256, 256>>>(aw);
    gat_main<<<dim3(IBLOCKS, JSPLIT), 256, SMEM_TOTAL>>>(adj);
    reduce_kernel<<<N_NODES / 4, 128>>>(out);
}